// round 4
// baseline (speedup 1.0000x reference)
#include <cuda_runtime.h>

#define BATCH 16
#define CH    256
#define IH    100
#define IW    100
#define NBOX  100
#define RH    40
#define RW    40
#define NCLS  599
#define CPB   4          // channels per CTA in resize/pool kernel

// Scratch (no allocations allowed)
__device__ float g_pooled[BATCH * NBOX * CH];   // [B][N][C]  (coalesced reads in k2)
__device__ int   g_counts[BATCH * NCLS];        // valid boxes per (b, cls)
__device__ int   g_precls[BATCH * NBOX];        // valid ? cls : -1

// Quantize one box (xyxy, image coords) to the 40x40 grid. Matches
// jnp.round (half-to-even) + clip semantics of the reference.
__device__ __forceinline__ int quantize_box(float4 bb, bool& valid) {
    const float s = 40.0f / 1024.0f;            // exact in fp32
    int x1 = max((int)rintf(bb.x * s), 0);
    int y1 = max((int)rintf(bb.y * s), 0);
    int x2 = min((int)rintf(bb.z * s), RW);
    int y2 = min((int)rintf(bb.w * s), RH);
    valid = (x1 < x2) && (y1 < y2);
    x1 = min(max(x1, 0), RW);  x2 = min(max(x2, 0), RW);
    y1 = min(max(y1, 0), RH);  y2 = min(max(y2, 0), RH);
    return x1 | (y1 << 8) | (x2 << 16) | (y2 << 24);
}

// ---------------------------------------------------------------------------
// Kernel 1: per (b, 4 channels) — bilinear 100->40 resize into smem, then
// direct box-sum pooling (boxes are <=5x5 cells on the 40x40 grid).
// The cbas==0 CTA of each batch also produces g_counts / g_precls.
// ---------------------------------------------------------------------------
__global__ __launch_bounds__(256) void resize_pool_kernel(
        const float* __restrict__ feat, const float* __restrict__ boxes,
        const int* __restrict__ gt) {
    __shared__ float res[CPB][RH * RW];         // 25.6 KB
    __shared__ int   s_box[NBOX];               // packed x1,y1,x2,y2 (0 if invalid)
    __shared__ float s_pool[NBOX][CPB];         // staged for float4 writes

    const int blk  = blockIdx.x;                // 0 .. BATCH*CH/CPB-1
    const int b    = blk / (CH / CPB);
    const int cbas = (blk % (CH / CPB)) * CPB;
    const int tid  = threadIdx.x;
    const bool meta_cta = (cbas == 0);

    // --- quantize this batch's boxes (threads 0..99) ---
    bool v_me = false;
    if (tid < NBOX) {
        float4 bb = __ldg((const float4*)boxes + b * NBOX + tid);
        int pk = quantize_box(bb, v_me);
        s_box[tid] = v_me ? pk : 0;             // invalid -> x1==x2==0
    }
    // --- meta CTA: zero this batch's class counts (before the barrier) ---
    if (meta_cta) {
        for (int i = tid; i < NCLS; i += 256) g_counts[b * NCLS + i] = 0;
    }

    // --- bilinear resize (half-pixel centers): src = 2.5*dst + 0.75 ---
    const float* __restrict__ in = feat + (size_t)(b * CH + cbas) * (IH * IW);
    for (int i = tid; i < RH * RW; i += 256) {
        int oy = i / RW, ox = i % RW;
        float sy = 2.5f * (float)oy + 0.75f;    // frac is exactly .75 or .25
        float sx = 2.5f * (float)ox + 0.75f;
        int y0 = (int)sy;  float fy = sy - (float)y0;
        int x0 = (int)sx;  float fx = sx - (float)x0;
        int off = y0 * IW + x0;
        float gx0 = 1.0f - fx, gy0 = 1.0f - fy;
        #pragma unroll
        for (int p = 0; p < CPB; p++) {
            const float* q = in + p * (IH * IW) + off;
            float v00 = __ldg(q),      v01 = __ldg(q + 1);
            float v10 = __ldg(q + IW), v11 = __ldg(q + IW + 1);
            res[p][i] = gy0 * (gx0 * v00 + fx * v01) + fy * (gx0 * v10 + fx * v11);
        }
    }
    __syncthreads();

    // --- meta CTA: per-class counts + per-box class tags (post-barrier) ---
    if (meta_cta && tid < NBOX) {
        int cls = __ldg(gt + b * NBOX + tid);
        g_precls[b * NBOX + tid] = v_me ? cls : -1;
        if (v_me) atomicAdd(&g_counts[b * NCLS + cls], 1);
    }

    // --- direct box-average pooling: work item = (plane, box), grid-stride ---
    for (int t = tid; t < NBOX * CPB; t += 256) {
        int n = t % NBOX;
        int p = t / NBOX;
        int pk = s_box[n];
        int x1 = pk & 0xFF, y1 = (pk >> 8) & 0xFF;
        int x2 = (pk >> 16) & 0xFF, y2 = (pk >> 24) & 0xFF;
        float out = 0.0f;
        if (x1 < x2) {                          // valid (invalid stored as 0)
            float s = 0.0f;
            const float* r = res[p];
            for (int y = y1; y < y2; y++) {
                float rs = 0.0f;
                for (int x = x1; x < x2; x++) rs += r[y * RW + x];
                s += rs;
            }
            out = s / (float)((y2 - y1) * (x2 - x1));
        }
        s_pool[n][p] = out;
    }
    __syncthreads();

    // --- transposed write: one float4 per box into [B][N][C] ---
    if (tid < NBOX) {
        float4 v4 = make_float4(s_pool[tid][0], s_pool[tid][1],
                                s_pool[tid][2], s_pool[tid][3]);
        *(float4*)(g_pooled + (size_t)(b * NBOX + tid) * CH + cbas) = v4;
    }
}

// ---------------------------------------------------------------------------
// Kernel 2: scatter-mean per (b, class). One CTA per (class, b); thread = channel.
// Empty classes (84%) exit after one broadcast load + a zero write.
// Non-empty classes compact matching boxes in ascending order (deterministic,
// matching segment_sum accumulation order), then sum cnt coalesced rows.
// ---------------------------------------------------------------------------
__global__ __launch_bounds__(CH) void class_mean_kernel(float* __restrict__ out) {
    const int cls = blockIdx.x;   // 0..598
    const int b   = blockIdx.y;   // 0..15
    const int tid = threadIdx.x;  // channel
    float* __restrict__ o = out + (size_t)(b * NCLS + cls) * CH + tid;

    const int cnt = __ldg(&g_counts[b * NCLS + cls]);   // uniform broadcast
    if (cnt == 0) { *o = 0.0f; return; }

    __shared__ int s_list[NBOX];
    __shared__ int s_wcnt[8];
    const int wid  = tid >> 5;
    const int lane = tid & 31;

    bool m = (tid < NBOX) && (__ldg(&g_precls[b * NBOX + tid]) == cls);
    unsigned bal = __ballot_sync(0xffffffffu, m);
    if (lane == 0) s_wcnt[wid] = __popc(bal);
    __syncthreads();
    if (m) {
        int base = 0;
        #pragma unroll
        for (int w = 0; w < 4; w++) base += (w < wid) ? s_wcnt[w] : 0;
        s_list[base + __popc(bal & ((1u << lane) - 1u))] = tid;   // ascending n
    }
    __syncthreads();

    float sum = 0.0f;
    for (int j = 0; j < cnt; j++)
        sum += __ldg(&g_pooled[(size_t)(b * NBOX + s_list[j]) * CH + tid]);
    *o = sum / (float)cnt;
}

// ---------------------------------------------------------------------------
extern "C" void kernel_launch(void* const* d_in, const int* in_sizes, int n_in,
                              void* d_out, int out_size) {
    const float* feat  = (const float*)d_in[0];   // [16,256,100,100] f32
    const float* boxes = (const float*)d_in[1];   // [16,100,4] f32
    const int*   gt    = (const int*)d_in[2];     // [16,100] i32
    float* out = (float*)d_out;                   // [16,599,256] f32

    resize_pool_kernel<<<BATCH * (CH / CPB), 256>>>(feat, boxes, gt);
    dim3 g2(NCLS, BATCH);
    class_mean_kernel<<<g2, CH>>>(out);
}